// round 9
// baseline (speedup 1.0000x reference)
#include <cuda_runtime.h>
#include <cuda_fp16.h>

// Problem constants (fixed by the dataset)
#define NN    50000
#define E0C   800000
#define HEADS 16
#define HD    8
#define HIDD  128

// ---------------- scratch (device globals, no allocation) ----------------
__device__ __align__(16) __half g_xh16[NN * HIDD];  // fp16 copy of x @ W (message path)
__device__ __align__(16) float  g_h[NN * HIDD];     // layer-1 output (layer-2 input)
__device__ __align__(16) float  g_als[NN * HEADS];
__device__ __align__(16) float  g_ald[NN * HEADS];

// CSR (by dst), built once per call.
// INVARIANT: g_deg is all-zero on entry to kernel_launch (zero-initialized at
// module load; csr_scan re-zeroes it after consuming). Deterministic per call.
__device__ int g_deg[NN];
__device__ int g_off[NN + 1];
__device__ int g_cur[NN];
__device__ int g_srclist[E0C];

// ---------------- CSR build -------------------------------------------------
__global__ void csr_hist_kernel(const int* __restrict__ ei) {
    int e = blockIdx.x * blockDim.x + threadIdx.x;
    if (e >= E0C) return;
    atomicAdd(&g_deg[__ldg(ei + E0C + e)], 1);
}

// single-block exclusive scan over NN degrees; re-zeros g_deg afterwards
__global__ void csr_scan_kernel() {
    __shared__ int partial[1024];
    const int t = threadIdx.x;
    const int CH = (NN + 1023) / 1024;   // 49
    const int start = t * CH;

    int sum = 0;
    for (int i = 0; i < CH; i++) {
        int n = start + i;
        if (n < NN) sum += g_deg[n];
    }
    partial[t] = sum;
    __syncthreads();
    for (int off = 1; off < 1024; off <<= 1) {
        int v = (t >= off) ? partial[t - off] : 0;
        __syncthreads();
        partial[t] += v;
        __syncthreads();
    }
    int run = (t == 0) ? 0 : partial[t - 1];
    for (int i = 0; i < CH; i++) {
        int n = start + i;
        if (n < NN) {
            int d = g_deg[n];
            g_off[n] = run;
            g_cur[n] = run;
            run += d;
            g_deg[n] = 0;   // restore invariant for next call
        }
    }
    if (t == 1023) g_off[NN] = run;
}

__global__ void csr_scatter_kernel(const int* __restrict__ ei) {
    int e = blockIdx.x * blockDim.x + threadIdx.x;
    if (e >= E0C) return;
    int src = __ldg(ei + e);
    int dst = __ldg(ei + E0C + e);
    int pos = atomicAdd(&g_cur[dst], 1);
    g_srclist[pos] = src;
}

// ---------------- tf32 tensor-core GEMM + fused logits + fp16 store --------
#define WS_PITCH 136   // words; 136 % 32 == 8 -> conflict-free frag loads
#define GEMM_ROWS 128
#define GEMM_SMEM_BYTES ((128 * WS_PITCH + 8 * WS_PITCH) * 4)

__device__ __forceinline__ unsigned f2tf32(float f) {
    unsigned r;
    asm("cvt.rna.tf32.f32 %0, %1;" : "=r"(r) : "f"(f));
    return r;
}

__device__ __forceinline__ void mma_tf32(float& d0, float& d1, float& d2, float& d3,
                                         unsigned a0, unsigned a1, unsigned a2, unsigned a3,
                                         unsigned b0, unsigned b1) {
    asm volatile(
        "mma.sync.aligned.m16n8k8.row.col.f32.tf32.tf32.f32 "
        "{%0,%1,%2,%3},{%4,%5,%6,%7},{%8,%9},{%0,%1,%2,%3};"
        : "+f"(d0), "+f"(d1), "+f"(d2), "+f"(d3)
        : "r"(a0), "r"(a1), "r"(a2), "r"(a3), "r"(b0), "r"(b1));
}

template <int LAYER>
__global__ void gemm_kernel(const float* __restrict__ X,
                            const float* __restrict__ W,
                            const float* __restrict__ a_src,
                            const float* __restrict__ a_dst, int M) {
    const float* A = (LAYER == 0) ? X : g_h;

    extern __shared__ unsigned smem_u[];
    unsigned* Ws  = smem_u;                    // [128][WS_PITCH] tf32 W (k-major)
    unsigned* Ast = smem_u + 128 * WS_PITCH;   // [8][WS_PITCH] tf32 A^T per k-step

    const int tid  = threadIdx.x;   // 256
    const int lane = tid & 31;
    const int w    = tid >> 5;      // warp 0..7
    const int g    = lane >> 2;     // group 0..7
    const int t    = lane & 3;      // thread-in-group 0..3
    const int row0 = blockIdx.x * GEMM_ROWS;

#pragma unroll
    for (int it = 0; it < 16; it++) {
        int v = tid + it * 256;
        int k = v >> 5;
        int n4 = (v & 31) << 2;
        float4 wv = *reinterpret_cast<const float4*>(W + (size_t)k * HIDD + n4);
        unsigned* p = Ws + k * WS_PITCH + n4;
        p[0] = f2tf32(wv.x); p[1] = f2tf32(wv.y);
        p[2] = f2tf32(wv.z); p[3] = f2tf32(wv.w);
    }
    __syncthreads();

    float acc[16][4];
#pragma unroll
    for (int j = 0; j < 16; j++)
#pragma unroll
        for (int c = 0; c < 4; c++) acc[j][c] = 0.f;

    for (int ks = 0; ks < 16; ks++) {
        const int k0 = ks * 8;
        {
            int r = tid >> 1;
            int c4 = (tid & 1) << 2;
            int grow = row0 + r;
            float4 av = make_float4(0.f, 0.f, 0.f, 0.f);
            if (grow < M)
                av = *reinterpret_cast<const float4*>(A + (size_t)grow * HIDD + k0 + c4);
            Ast[(c4 + 0) * WS_PITCH + r] = f2tf32(av.x);
            Ast[(c4 + 1) * WS_PITCH + r] = f2tf32(av.y);
            Ast[(c4 + 2) * WS_PITCH + r] = f2tf32(av.z);
            Ast[(c4 + 3) * WS_PITCH + r] = f2tf32(av.w);
        }
        __syncthreads();

        unsigned a0 = Ast[t * WS_PITCH + 16 * w + g];
        unsigned a1 = Ast[t * WS_PITCH + 16 * w + g + 8];
        unsigned a2 = Ast[(t + 4) * WS_PITCH + 16 * w + g];
        unsigned a3 = Ast[(t + 4) * WS_PITCH + 16 * w + g + 8];
        const unsigned* wb0 = Ws + (k0 + t) * WS_PITCH + g;
        const unsigned* wb1 = Ws + (k0 + t + 4) * WS_PITCH + g;
#pragma unroll
        for (int j = 0; j < 16; j++) {
            unsigned b0 = wb0[8 * j];
            unsigned b1 = wb1[8 * j];
            mma_tf32(acc[j][0], acc[j][1], acc[j][2], acc[j][3],
                     a0, a1, a2, a3, b0, b1);
        }
        __syncthreads();
    }

    const int rw = row0 + 16 * w;
#pragma unroll
    for (int j = 0; j < 16; j++) {
        float c0 = acc[j][0], c1 = acc[j][1], c2 = acc[j][2], c3 = acc[j][3];
        int colb = 8 * j + 2 * t;
        float2 sv = __ldg(reinterpret_cast<const float2*>(a_src + colb));
        float2 dv = __ldg(reinterpret_cast<const float2*>(a_dst + colb));
        float s0 = c0 * sv.x + c1 * sv.y;
        float d0 = c0 * dv.x + c1 * dv.y;
        float s1 = c2 * sv.x + c3 * sv.y;
        float d1 = c2 * dv.x + c3 * dv.y;
        s0 += __shfl_xor_sync(0xffffffffu, s0, 1);
        s0 += __shfl_xor_sync(0xffffffffu, s0, 2);
        d0 += __shfl_xor_sync(0xffffffffu, d0, 1);
        d0 += __shfl_xor_sync(0xffffffffu, d0, 2);
        s1 += __shfl_xor_sync(0xffffffffu, s1, 1);
        s1 += __shfl_xor_sync(0xffffffffu, s1, 2);
        d1 += __shfl_xor_sync(0xffffffffu, d1, 1);
        d1 += __shfl_xor_sync(0xffffffffu, d1, 2);

        int r0v = rw + g, r1v = rw + g + 8;
        if (r0v < M) {
            __half2 p = __floats2half2_rn(c0, c1);
            *reinterpret_cast<__half2*>(g_xh16 + (size_t)r0v * HIDD + colb) = p;
            if (t == 0) {
                g_als[r0v * HEADS + j] = s0;
                g_ald[r0v * HEADS + j] = d0;
            }
        }
        if (r1v < M) {
            __half2 p = __floats2half2_rn(c2, c3);
            *reinterpret_cast<__half2*>(g_xh16 + (size_t)r1v * HIDD + colb) = p;
            if (t == 0) {
                g_als[r1v * HEADS + j] = s1;
                g_ald[r1v * HEADS + j] = d1;
            }
        }
    }
}

// ---------------- fused aggregation: half-warp x 4-deep pipeline -----------
// One warp per dst node. Lane l: hl = l&15 = head; lane owns that head's 8
// output cols. Even half-warp takes neighbor groups [8m, 8m+4), odd takes
// [8m+4, 8m+8). Inner stage issues 4 independent als + 4 independent xh
// loads up-front (MLP >= 8), then consumes. shfl_down(16) combine at end.
template <int LAYER>
__global__ void aggregate_kernel(const float* __restrict__ bias,
                                 float* __restrict__ outbuf) {
    const int warp = (blockIdx.x * blockDim.x + threadIdx.x) >> 5;
    if (warp >= NN) return;
    const int lane = threadIdx.x & 31;
    const int hl   = lane & 15;        // head owned by this lane
    const int odd  = lane >> 4;
    const int n = warp;

    const float ald_h = __ldg(g_ald + n * HEADS + hl);

    float acc[8];
    float denom;

    // self loop: even half-warp only (odd contributes ex=0)
    {
        float v = __ldg(g_als + n * HEADS + hl) + ald_h;
        float lr = v > 0.f ? v : 0.2f * v;
        float ex = odd ? 0.f : __expf(lr);
        uint4 raw = __ldg(reinterpret_cast<const uint4*>(g_xh16 + (size_t)n * HIDD + hl * 8));
        const __half2* hp = reinterpret_cast<const __half2*>(&raw);
#pragma unroll
        for (int i = 0; i < 4; i++) {
            float2 f = __half22float2(hp[i]);
            acc[2 * i]     = ex * f.x;
            acc[2 * i + 1] = ex * f.y;
        }
        denom = ex;
    }

    const int beg = __ldg(g_off + n);
    const int end = __ldg(g_off + n + 1);
    const int deg = end - beg;

    for (int j0 = 0; j0 < deg; j0 += 32) {
        int myidx = beg + j0 + lane;
        int s = (myidx < end) ? __ldg(g_srclist + myidx) : 0;
        int cnt = min(32, deg - j0);
        // uniform trip count across the warp; half-warps take alternating
        // groups of 4 within each block of 8
        for (int m = 0; m < cnt; m += 8) {
            const int base = m + odd * 4;
            int src[4];
            bool val[4];
#pragma unroll
            for (int i = 0; i < 4; i++) {
                src[i] = __shfl_sync(0xffffffffu, s, (base + i) & 31);
                val[i] = (base + i) < cnt;
            }
            // front-batched independent loads (MLP 8)
            float a[4];
            uint4 x[4];
#pragma unroll
            for (int i = 0; i < 4; i++)
                a[i] = __ldg(g_als + src[i] * HEADS + hl);
#pragma unroll
            for (int i = 0; i < 4; i++)
                x[i] = __ldg(reinterpret_cast<const uint4*>(
                          g_xh16 + (size_t)src[i] * HIDD + hl * 8));
            // consume
#pragma unroll
            for (int i = 0; i < 4; i++) {
                float v = a[i] + ald_h;
                float lr = v > 0.f ? v : 0.2f * v;
                float ex = val[i] ? __expf(lr) : 0.f;
                const __half2* hp = reinterpret_cast<const __half2*>(&x[i]);
#pragma unroll
                for (int q = 0; q < 4; q++) {
                    float2 f = __half22float2(hp[q]);
                    acc[2 * q]     = fmaf(ex, f.x, acc[2 * q]);
                    acc[2 * q + 1] = fmaf(ex, f.y, acc[2 * q + 1]);
                }
                denom += ex;
            }
        }
    }

    // combine the two half-warps
#pragma unroll
    for (int i = 0; i < 8; i++)
        acc[i] += __shfl_down_sync(0xffffffffu, acc[i], 16);
    denom += __shfl_down_sync(0xffffffffu, denom, 16);

    if (!odd) {
        float inv = 1.f / (denom + 1e-16f);
        float4 b0 = *reinterpret_cast<const float4*>(bias + hl * 8);
        float4 b1 = *reinterpret_cast<const float4*>(bias + hl * 8 + 4);
        float4 r0, r1;
        r0.x = acc[0] * inv + b0.x;
        r0.y = acc[1] * inv + b0.y;
        r0.z = acc[2] * inv + b0.z;
        r0.w = acc[3] * inv + b0.w;
        r1.x = acc[4] * inv + b1.x;
        r1.y = acc[5] * inv + b1.y;
        r1.z = acc[6] * inv + b1.z;
        r1.w = acc[7] * inv + b1.w;
        if (LAYER == 0) {
            r0.x = r0.x > 0.f ? r0.x : expm1f(r0.x);
            r0.y = r0.y > 0.f ? r0.y : expm1f(r0.y);
            r0.z = r0.z > 0.f ? r0.z : expm1f(r0.z);
            r0.w = r0.w > 0.f ? r0.w : expm1f(r0.w);
            r1.x = r1.x > 0.f ? r1.x : expm1f(r1.x);
            r1.y = r1.y > 0.f ? r1.y : expm1f(r1.y);
            r1.z = r1.z > 0.f ? r1.z : expm1f(r1.z);
            r1.w = r1.w > 0.f ? r1.w : expm1f(r1.w);
            *reinterpret_cast<float4*>(g_h + (size_t)n * HIDD + hl * 8)     = r0;
            *reinterpret_cast<float4*>(g_h + (size_t)n * HIDD + hl * 8 + 4) = r1;
        } else {
            *reinterpret_cast<float4*>(outbuf + (size_t)n * HIDD + hl * 8)     = r0;
            *reinterpret_cast<float4*>(outbuf + (size_t)n * HIDD + hl * 8 + 4) = r1;
        }
    }
}

// ---------------- launch ------------------------------------------------------
extern "C" void kernel_launch(void* const* d_in, const int* in_sizes, int n_in,
                              void* d_out, int out_size) {
    const float* x   = (const float*)d_in[0];
    const int*   ei  = (const int*)d_in[1];
    const float* W1  = (const float*)d_in[2];
    const float* as1 = (const float*)d_in[3];
    const float* ad1 = (const float*)d_in[4];
    const float* b1  = (const float*)d_in[5];
    const float* W2  = (const float*)d_in[6];
    const float* as2 = (const float*)d_in[7];
    const float* ad2 = (const float*)d_in[8];
    const float* b2  = (const float*)d_in[9];
    float* out = (float*)d_out;

    cudaFuncSetAttribute(gemm_kernel<0>, cudaFuncAttributeMaxDynamicSharedMemorySize,
                         GEMM_SMEM_BYTES);
    cudaFuncSetAttribute(gemm_kernel<1>, cudaFuncAttributeMaxDynamicSharedMemorySize,
                         GEMM_SMEM_BYTES);

    const int TB = 256;
    const int gGemm = (NN + GEMM_ROWS - 1) / GEMM_ROWS;
    const int gEdge = (E0C + TB - 1) / TB;
    const int gAgg  = (NN * 32 + TB - 1) / TB;   // one warp per node

    // ---- CSR build (g_deg zero-invariant maintained by csr_scan) ----
    csr_hist_kernel<<<gEdge, TB>>>(ei);
    csr_scan_kernel<<<1, 1024>>>();
    csr_scatter_kernel<<<gEdge, TB>>>(ei);

    // ---- layer 1 ----
    gemm_kernel<0><<<gGemm, TB, GEMM_SMEM_BYTES>>>(x, W1, as1, ad1, NN);
    aggregate_kernel<0><<<gAgg, TB>>>(b1, nullptr);

    // ---- layer 2 ----
    gemm_kernel<1><<<gGemm, TB, GEMM_SMEM_BYTES>>>(nullptr, W2, as2, ad2, NN);
    aggregate_kernel<1><<<gAgg, TB>>>(b2, out);
}